// round 3
// baseline (speedup 1.0000x reference)
#include <cuda_runtime.h>
#include <math.h>

// Problem constants (fixed by the dataset)
#define B_  4
#define S_  2048
#define D_  1024
#define H_  16
#define DK_ 64      // per-head key/value dim

// Scratch (device globals — no allocation allowed in kernel_launch)
__device__ float g_q[B_ * H_ * S_ * DK_];     // [B,H,S,DK] 32 MB
__device__ float g_k[B_ * H_ * S_ * DK_];     // 32 MB
__device__ float g_v[B_ * H_ * S_ * DK_];     // 32 MB
__device__ float g_attn[B_ * S_ * H_ * DK_];  // [B,S,H*DV] 32 MB

// ---------------------------------------------------------------------------
// Kernel 1: per-head projection  out[b,h,s,k] = sum_d x[b,s,d] * W[h,d,k]
// Block tile: 128 (s) x 64 (k = full DK), BK=16. 256 threads, 8x4 microtile.
// which: 0 -> g_q, 1 -> g_k, 2 -> g_v
// ---------------------------------------------------------------------------
__global__ __launch_bounds__(256) void proj_kernel(const float* __restrict__ x,
                                                   const float* __restrict__ W,
                                                   int which) {
    float* out = (which == 0) ? g_q : (which == 1) ? g_k : g_v;

    const int h  = blockIdx.y;
    const int b  = blockIdx.z;
    const int m0 = blockIdx.x * 128;  // s offset

    const float* xb   = x + (size_t)b * S_ * D_;
    const float* Wh   = W + (size_t)h * D_ * DK_;
    float*       outh = out + (size_t)(b * H_ + h) * S_ * DK_;

    __shared__ float As[16][128];  // [k][m]  (transposed x tile)
    __shared__ float Bs[16][64];   // [k][n]

    const int tid = threadIdx.x;
    const int tx  = tid & 15;   // col group: 4 cols
    const int ty  = tid >> 4;   // row group: 8 rows

    float acc[8][4];
    #pragma unroll
    for (int i = 0; i < 8; i++)
        #pragma unroll
        for (int j = 0; j < 4; j++) acc[i][j] = 0.0f;

    for (int k0 = 0; k0 < D_; k0 += 16) {
        // Load x tile (128 x 16), store transposed
        {
            const int r   = tid >> 2;        // 0..63
            const int kk4 = (tid & 3) * 4;   // 0,4,8,12
            #pragma unroll
            for (int p = 0; p < 2; p++) {
                float4 t = *(const float4*)&xb[(size_t)(m0 + r + p * 64) * D_ + k0 + kk4];
                As[kk4 + 0][r + p * 64] = t.x;
                As[kk4 + 1][r + p * 64] = t.y;
                As[kk4 + 2][r + p * 64] = t.z;
                As[kk4 + 3][r + p * 64] = t.w;
            }
        }
        // Load W tile (16 x 64), direct
        {
            const int kk = tid >> 4;          // 0..15
            const int c  = (tid & 15) * 4;    // 0..60
            *(float4*)&Bs[kk][c] = *(const float4*)&Wh[(size_t)(k0 + kk) * DK_ + c];
        }
        __syncthreads();

        #pragma unroll
        for (int kk = 0; kk < 16; kk++) {
            float a[8], bb[4];
            *(float4*)&a[0] = *(const float4*)&As[kk][ty * 8];
            *(float4*)&a[4] = *(const float4*)&As[kk][ty * 8 + 4];
            *(float4*)&bb[0] = *(const float4*)&Bs[kk][tx * 4];
            #pragma unroll
            for (int i = 0; i < 8; i++)
                #pragma unroll
                for (int j = 0; j < 4; j++)
                    acc[i][j] = fmaf(a[i], bb[j], acc[i][j]);
        }
        __syncthreads();
    }

    #pragma unroll
    for (int i = 0; i < 8; i++) {
        const int r = m0 + ty * 8 + i;
        *(float4*)&outh[(size_t)r * DK_ + tx * 4] = *(float4*)&acc[i][0];
    }
}

// ---------------------------------------------------------------------------
// Kernel 2: flash attention per (b,h). Block handles 64 q-rows, streams key
// tiles of 64. 256 threads; 4x4 microtiles for both GEMMs. smem = 48 KB.
// KPs buffer is reused: K-phase [d][t], then P-phase [t][q].
// ---------------------------------------------------------------------------
__global__ __launch_bounds__(256) void flash_kernel(float* __restrict__ dummy_unused) {
    const int h  = blockIdx.y;
    const int b  = blockIdx.z;
    const int q0 = blockIdx.x * 64;

    const size_t bh = (size_t)(b * H_ + h) * S_;
    const float* qh = g_q + bh * DK_;
    const float* kh = g_k + bh * DK_;
    const float* vh = g_v + bh * DK_;

    __shared__ float Qs[64][64];   // [d][q]  (Q transposed)
    __shared__ float KPs[64][64];  // K phase: [d][t]; P phase: [t][q]
    __shared__ float Vs[64][64];   // [t][dv]

    const int tid = threadIdx.x;
    const int tx  = tid & 15;   // 4 cols (t in gemm1, dv in gemm2)
    const int ty  = tid >> 4;   // 4 rows (q)

    // Load Q tile transposed: each thread handles one row chunk
    {
        const int r  = tid >> 2;         // 0..63 (q row)
        const int d4 = (tid & 3) * 16;   // dim chunk
        #pragma unroll
        for (int p = 0; p < 4; p++) {
            float4 t = *(const float4*)&qh[(size_t)(q0 + r) * DK_ + d4 + p * 4];
            Qs[d4 + p * 4 + 0][r] = t.x;
            Qs[d4 + p * 4 + 1][r] = t.y;
            Qs[d4 + p * 4 + 2][r] = t.z;
            Qs[d4 + p * 4 + 3][r] = t.w;
        }
    }

    float O[4][4];
    float m_i[4], l_i[4];
    #pragma unroll
    for (int i = 0; i < 4; i++) {
        m_i[i] = -INFINITY;
        l_i[i] = 0.0f;
        #pragma unroll
        for (int j = 0; j < 4; j++) O[i][j] = 0.0f;
    }

    const float scale = 0.125f;  // 1/sqrt(64)

    for (int t0 = 0; t0 < S_; t0 += 64) {
        __syncthreads();  // prev GEMM2 done reading KPs/Vs; Q load visible (1st iter)
        // Load K tile transposed [d][t] and V tile direct [t][dv]
        {
            const int t  = tid >> 2;
            const int d4 = (tid & 3) * 16;
            #pragma unroll
            for (int p = 0; p < 4; p++) {
                float4 kk = *(const float4*)&kh[(size_t)(t0 + t) * DK_ + d4 + p * 4];
                KPs[d4 + p * 4 + 0][t] = kk.x;
                KPs[d4 + p * 4 + 1][t] = kk.y;
                KPs[d4 + p * 4 + 2][t] = kk.z;
                KPs[d4 + p * 4 + 3][t] = kk.w;
                *(float4*)&Vs[t][d4 + p * 4] =
                    *(const float4*)&vh[(size_t)(t0 + t) * DK_ + d4 + p * 4];
            }
        }
        __syncthreads();

        // GEMM1: s[q][t] = Q @ K^T
        float s[4][4];
        #pragma unroll
        for (int i = 0; i < 4; i++)
            #pragma unroll
            for (int j = 0; j < 4; j++) s[i][j] = 0.0f;

        #pragma unroll
        for (int dd = 0; dd < 64; dd++) {
            float a[4], bb[4];
            *(float4*)&a[0]  = *(const float4*)&Qs[dd][ty * 4];
            *(float4*)&bb[0] = *(const float4*)&KPs[dd][tx * 4];
            #pragma unroll
            for (int i = 0; i < 4; i++)
                #pragma unroll
                for (int j = 0; j < 4; j++)
                    s[i][j] = fmaf(a[i], bb[j], s[i][j]);
        }

        // Online softmax update (row reductions across the 16 tx lanes)
        float p[4][4], alpha[4];
        #pragma unroll
        for (int i = 0; i < 4; i++) {
            float mx = fmaxf(fmaxf(s[i][0], s[i][1]), fmaxf(s[i][2], s[i][3])) * scale;
            #pragma unroll
            for (int off = 8; off >= 1; off >>= 1)
                mx = fmaxf(mx, __shfl_xor_sync(0xffffffffu, mx, off));
            const float mnew = fmaxf(m_i[i], mx);
            alpha[i] = __expf(m_i[i] - mnew);
            float rs = 0.0f;
            #pragma unroll
            for (int j = 0; j < 4; j++) {
                p[i][j] = __expf(s[i][j] * scale - mnew);
                rs += p[i][j];
            }
            #pragma unroll
            for (int off = 8; off >= 1; off >>= 1)
                rs += __shfl_xor_sync(0xffffffffu, rs, off);
            l_i[i] = l_i[i] * alpha[i] + rs;
            m_i[i] = mnew;
        }

        __syncthreads();  // everyone done reading KPs as K

        // Write P into KPs as [t][q]; rescale O
        #pragma unroll
        for (int i = 0; i < 4; i++) {
            #pragma unroll
            for (int j = 0; j < 4; j++) {
                KPs[tx * 4 + j][ty * 4 + i] = p[i][j];
                O[i][j] *= alpha[i];
            }
        }
        __syncthreads();

        // GEMM2: O[q][dv] += P @ V
        #pragma unroll
        for (int tt = 0; tt < 64; tt++) {
            float a[4], bb[4];
            *(float4*)&a[0]  = *(const float4*)&KPs[tt][ty * 4];
            *(float4*)&bb[0] = *(const float4*)&Vs[tt][tx * 4];
            #pragma unroll
            for (int i = 0; i < 4; i++)
                #pragma unroll
                for (int j = 0; j < 4; j++)
                    O[i][j] = fmaf(a[i], bb[j], O[i][j]);
        }
    }

    // Epilogue: normalize and write to concat layout [B,S,H*DV]
    #pragma unroll
    for (int i = 0; i < 4; i++) {
        const float inv = 1.0f / l_i[i];
        float4 r;
        r.x = O[i][0] * inv; r.y = O[i][1] * inv;
        r.z = O[i][2] * inv; r.w = O[i][3] * inv;
        const int row = q0 + ty * 4 + i;
        *(float4*)&g_attn[(size_t)(b * S_ + row) * (H_ * DK_) + h * DK_ + tx * 4] = r;
    }
}

// ---------------------------------------------------------------------------
// Kernel 3: output projection  out = g_attn[8192,1024] @ W_O[1024,1024]
// Block tile 128x128, BK=16, 256 threads, 8x8 microtile.
// ---------------------------------------------------------------------------
__global__ __launch_bounds__(256) void outproj_kernel(const float* __restrict__ WO,
                                                      float* __restrict__ out) {
    const int m0 = blockIdx.x * 128;
    const int n0 = blockIdx.y * 128;

    __shared__ float As[16][128];  // [k][m] (transposed attn tile)
    __shared__ float Bs[16][128];  // [k][n]

    const int tid = threadIdx.x;
    const int tx  = tid & 15;   // 8 cols
    const int ty  = tid >> 4;   // 8 rows

    float acc[8][8];
    #pragma unroll
    for (int i = 0; i < 8; i++)
        #pragma unroll
        for (int j = 0; j < 8; j++) acc[i][j] = 0.0f;

    const int NCOL = H_ * DK_;  // 1024

    for (int k0 = 0; k0 < NCOL; k0 += 16) {
        {
            const int r   = tid >> 2;
            const int kk4 = (tid & 3) * 4;
            #pragma unroll
            for (int p = 0; p < 2; p++) {
                float4 t = *(const float4*)&g_attn[(size_t)(m0 + r + p * 64) * NCOL + k0 + kk4];
                As[kk4 + 0][r + p * 64] = t.x;
                As[kk4 + 1][r + p * 64] = t.y;
                As[kk4 + 2][r + p * 64] = t.z;
                As[kk4 + 3][r + p * 64] = t.w;
            }
        }
        {
            #pragma unroll
            for (int p = 0; p < 2; p++) {
                const int idx = tid + p * 256;
                const int kk  = idx >> 5;         // 0..15
                const int c   = (idx & 31) * 4;   // 0..124
                *(float4*)&Bs[kk][c] = *(const float4*)&WO[(size_t)(k0 + kk) * D_ + n0 + c];
            }
        }
        __syncthreads();

        #pragma unroll
        for (int kk = 0; kk < 16; kk++) {
            float a[8], bb[8];
            *(float4*)&a[0]  = *(const float4*)&As[kk][ty * 8];
            *(float4*)&a[4]  = *(const float4*)&As[kk][ty * 8 + 4];
            *(float4*)&bb[0] = *(const float4*)&Bs[kk][tx * 8];
            *(float4*)&bb[4] = *(const float4*)&Bs[kk][tx * 8 + 4];
            #pragma unroll
            for (int i = 0; i < 8; i++)
                #pragma unroll
                for (int j = 0; j < 8; j++)
                    acc[i][j] = fmaf(a[i], bb[j], acc[i][j]);
        }
        __syncthreads();
    }

    #pragma unroll
    for (int i = 0; i < 8; i++) {
        const int r = m0 + ty * 8 + i;
        *(float4*)&out[(size_t)r * D_ + n0 + tx * 8]     = *(float4*)&acc[i][0];
        *(float4*)&out[(size_t)r * D_ + n0 + tx * 8 + 4] = *(float4*)&acc[i][4];
    }
}

// ---------------------------------------------------------------------------
extern "C" void kernel_launch(void* const* d_in, const int* in_sizes, int n_in,
                              void* d_out, int out_size) {
    const float* x  = (const float*)d_in[0];
    const float* wq = (const float*)d_in[1];
    const float* wk = (const float*)d_in[2];
    const float* wv = (const float*)d_in[3];
    const float* wo = (const float*)d_in[4];
    float* out = (float*)d_out;

    dim3 gp(S_ / 128, H_, B_);     // 16,16,4
    proj_kernel<<<gp, 256>>>(x, wq, 0);
    proj_kernel<<<gp, 256>>>(x, wk, 1);
    proj_kernel<<<gp, 256>>>(x, wv, 2);

    dim3 gf(S_ / 64, H_, B_);      // 32,16,4
    flash_kernel<<<gf, 256>>>(nullptr);

    dim3 go((B_ * S_) / 128, D_ / 128);  // 64,8
    outproj_kernel<<<go, 256>>>(wo, out);
}

// round 9
// speedup vs baseline: 1.5060x; 1.5060x over previous
#include <cuda_runtime.h>
#include <cuda_bf16.h>
#include <cstdint>
#include <math.h>

#define B_  4
#define S_  2048
#define D_  1024
#define H_  16
#define DK_ 64

// ------------------------- device global scratch ---------------------------
__device__ __align__(16) float g_q[B_ * H_ * S_ * DK_];
__device__ __align__(16) float g_k[B_ * H_ * S_ * DK_];
__device__ __align__(16) float g_v[B_ * H_ * S_ * DK_];

__device__ __align__(16) __nv_bfloat16 g_x_hi[B_ * S_ * D_];
__device__ __align__(16) __nv_bfloat16 g_x_lo[B_ * S_ * D_];
__device__ __align__(16) __nv_bfloat16 g_attn_hi[B_ * S_ * D_];
__device__ __align__(16) __nv_bfloat16 g_attn_lo[B_ * S_ * D_];

// Weights stored transposed: [h][n][k] (proj) / [n][k] (out-proj), bf16 hi/lo
__device__ __align__(16) __nv_bfloat16 g_wq_hi[H_ * DK_ * D_];
__device__ __align__(16) __nv_bfloat16 g_wq_lo[H_ * DK_ * D_];
__device__ __align__(16) __nv_bfloat16 g_wk_hi[H_ * DK_ * D_];
__device__ __align__(16) __nv_bfloat16 g_wk_lo[H_ * DK_ * D_];
__device__ __align__(16) __nv_bfloat16 g_wv_hi[H_ * DK_ * D_];
__device__ __align__(16) __nv_bfloat16 g_wv_lo[H_ * DK_ * D_];
__device__ __align__(16) __nv_bfloat16 g_wo_hi[D_ * D_];
__device__ __align__(16) __nv_bfloat16 g_wo_lo[D_ * D_];

// ------------------------------ PTX helpers --------------------------------
__device__ __forceinline__ uint32_t smem_u32(const void* p) {
    uint32_t a;
    asm("{ .reg .u64 t; cvta.to.shared.u64 t, %1; cvt.u32.u64 %0, t; }" : "=r"(a) : "l"(p));
    return a;
}
__device__ __forceinline__ void cp16(uint32_t s, const void* g) {
    asm volatile("cp.async.cg.shared.global [%0], [%1], 16;" :: "r"(s), "l"(g));
}
#define CP_COMMIT() asm volatile("cp.async.commit_group;" ::: "memory")
#define CP_WAIT(n)  asm volatile("cp.async.wait_group %0;" :: "n"(n) : "memory")

__device__ __forceinline__ void ldmx4(uint32_t* r, uint32_t a) {
    asm volatile("ldmatrix.sync.aligned.m8n8.x4.shared.b16 {%0,%1,%2,%3}, [%4];"
                 : "=r"(r[0]), "=r"(r[1]), "=r"(r[2]), "=r"(r[3]) : "r"(a));
}
__device__ __forceinline__ void mma16816(float* d, const uint32_t* a, uint32_t b0, uint32_t b1) {
    asm volatile(
        "mma.sync.aligned.m16n8k16.row.col.f32.bf16.bf16.f32 "
        "{%0,%1,%2,%3}, {%4,%5,%6,%7}, {%8,%9}, {%0,%1,%2,%3};"
        : "+f"(d[0]), "+f"(d[1]), "+f"(d[2]), "+f"(d[3])
        : "r"(a[0]), "r"(a[1]), "r"(a[2]), "r"(a[3]), "r"(b0), "r"(b1));
}

// packed f32x2 math (assembles at compute_103 — verified in R5 compile log)
__device__ __forceinline__ unsigned long long pk2(float lo, float hi) {
    unsigned long long r;
    asm("mov.b64 %0, {%1,%2};" : "=l"(r) : "r"(__float_as_uint(lo)), "r"(__float_as_uint(hi)));
    return r;
}
__device__ __forceinline__ void upk2(unsigned long long v, float& lo, float& hi) {
    unsigned int a, b;
    asm("mov.b64 {%0,%1}, %2;" : "=r"(a), "=r"(b) : "l"(v));
    lo = __uint_as_float(a); hi = __uint_as_float(b);
}
__device__ __forceinline__ unsigned long long fma2(unsigned long long a, unsigned long long b,
                                                   unsigned long long c) {
    unsigned long long d;
    asm("fma.rn.f32x2 %0, %1, %2, %3;" : "=l"(d) : "l"(a), "l"(b), "l"(c));
    return d;
}
__device__ __forceinline__ unsigned long long mul2(unsigned long long a, unsigned long long b) {
    unsigned long long d;
    asm("mul.rn.f32x2 %0, %1, %2;" : "=l"(d) : "l"(a), "l"(b));
    return d;
}

__device__ __forceinline__ void split_bf16(float v, uint16_t& h, uint16_t& l) {
    __nv_bfloat16 hb = __float2bfloat16_rn(v);
    __nv_bfloat16 lb = __float2bfloat16_rn(v - __bfloat162float(hb));
    h = __bfloat16_as_ushort(hb);
    l = __bfloat16_as_ushort(lb);
}

// ------------------------------ prep kernels -------------------------------
__global__ __launch_bounds__(256) void conv_x_kernel(const float4* __restrict__ x) {
    size_t i = (size_t)blockIdx.x * 256 + threadIdx.x;  // over B*S*D/4
    float4 v = x[i];
    uint16_t h0, h1, h2, h3, l0, l1, l2, l3;
    split_bf16(v.x, h0, l0); split_bf16(v.y, h1, l1);
    split_bf16(v.z, h2, l2); split_bf16(v.w, h3, l3);
    uint2 hv, lv;
    hv.x = (uint32_t)h0 | ((uint32_t)h1 << 16); hv.y = (uint32_t)h2 | ((uint32_t)h3 << 16);
    lv.x = (uint32_t)l0 | ((uint32_t)l1 << 16); lv.y = (uint32_t)l2 | ((uint32_t)l3 << 16);
    ((uint2*)g_x_hi)[i] = hv;
    ((uint2*)g_x_lo)[i] = lv;
}

// W[h][d][n] -> [h][n][k=d] bf16 hi/lo (transpose, one-time)
__global__ __launch_bounds__(256) void conv_w_kernel(const float* __restrict__ W, int wsel) {
    __nv_bfloat16* bhi = (wsel == 0) ? g_wq_hi : (wsel == 1) ? g_wk_hi : g_wv_hi;
    __nv_bfloat16* blo = (wsel == 0) ? g_wq_lo : (wsel == 1) ? g_wk_lo : g_wv_lo;
    int u = blockIdx.x * 256 + threadIdx.x;   // H*64*128 = 131072
    int k8 = u & 127;                         // k-group of 8
    int n  = (u >> 7) & 63;
    int h  = u >> 13;
    const float* src = W + ((size_t)h * D_ + k8 * 8) * DK_ + n;
    uint16_t hh[8], ll[8];
    #pragma unroll
    for (int i = 0; i < 8; i++) split_bf16(src[(size_t)i * DK_], hh[i], ll[i]);
    uint4 vh, vl;
    vh.x = (uint32_t)hh[0] | ((uint32_t)hh[1] << 16); vh.y = (uint32_t)hh[2] | ((uint32_t)hh[3] << 16);
    vh.z = (uint32_t)hh[4] | ((uint32_t)hh[5] << 16); vh.w = (uint32_t)hh[6] | ((uint32_t)hh[7] << 16);
    vl.x = (uint32_t)ll[0] | ((uint32_t)ll[1] << 16); vl.y = (uint32_t)ll[2] | ((uint32_t)ll[3] << 16);
    vl.z = (uint32_t)ll[4] | ((uint32_t)ll[5] << 16); vl.w = (uint32_t)ll[6] | ((uint32_t)ll[7] << 16);
    size_t dst = ((size_t)h * 64 + n) * D_ + k8 * 8;
    *(uint4*)(bhi + dst) = vh;
    *(uint4*)(blo + dst) = vl;
}

// W_O[k][col] -> [n=col][k] bf16 hi/lo
__global__ __launch_bounds__(256) void conv_wo_kernel(const float* __restrict__ W) {
    int u = blockIdx.x * 256 + threadIdx.x;   // 1024*128 = 131072
    int k8 = u & 127;
    int n  = u >> 7;
    const float* src = W + (size_t)(k8 * 8) * D_ + n;
    uint16_t hh[8], ll[8];
    #pragma unroll
    for (int i = 0; i < 8; i++) split_bf16(src[(size_t)i * D_], hh[i], ll[i]);
    uint4 vh, vl;
    vh.x = (uint32_t)hh[0] | ((uint32_t)hh[1] << 16); vh.y = (uint32_t)hh[2] | ((uint32_t)hh[3] << 16);
    vh.z = (uint32_t)hh[4] | ((uint32_t)hh[5] << 16); vh.w = (uint32_t)hh[6] | ((uint32_t)hh[7] << 16);
    vl.x = (uint32_t)ll[0] | ((uint32_t)ll[1] << 16); vl.y = (uint32_t)ll[2] | ((uint32_t)ll[3] << 16);
    vl.z = (uint32_t)ll[4] | ((uint32_t)ll[5] << 16); vl.w = (uint32_t)ll[6] | ((uint32_t)ll[7] << 16);
    size_t dst = (size_t)n * D_ + k8 * 8;
    *(uint4*)(g_wo_hi + dst) = vh;
    *(uint4*)(g_wo_lo + dst) = vl;
}

// ------------------- mma.sync bf16x3 GEMM (proj + outproj) -----------------
// CTA: 256 thr (8 warps, 4m x 2n), C tile 128m x 128n, K=1024 in 64 chunks of
// 16, cp.async double-buffered. LDA=24 bf16 rows (48B) -> conflict-free
// ldmatrix. mode 0/1/2: QKV proj (C = g_q/k/v); mode 3: out-proj (C = d_out).
#define LDA 24
#define STAGE_BYTES (4 * 128 * LDA * 2)   // 24576

__global__ __launch_bounds__(256) void gemm_kernel(float* __restrict__ Cext, int mode) {
    __shared__ __align__(16) __nv_bfloat16 smem[2][4][128 * LDA];  // 49152 B

    const int tid  = threadIdx.x;
    const int wid  = tid >> 5;
    const int lane = tid & 31;
    const int wm   = wid >> 1;   // 0..3
    const int wn   = wid & 1;    // 0..1

    const __nv_bfloat16 *Ah, *Al, *Bh, *Bl;
    float* C;
    if (mode == 0)      { Ah = g_x_hi;    Al = g_x_lo;    Bh = g_wq_hi; Bl = g_wq_lo; C = g_q; }
    else if (mode == 1) { Ah = g_x_hi;    Al = g_x_lo;    Bh = g_wk_hi; Bl = g_wk_lo; C = g_k; }
    else if (mode == 2) { Ah = g_x_hi;    Al = g_x_lo;    Bh = g_wv_hi; Bl = g_wv_lo; C = g_v; }
    else                { Ah = g_attn_hi; Al = g_attn_lo; Bh = g_wo_hi; Bl = g_wo_lo; C = Cext; }

    const int mg = (mode < 3) ? (blockIdx.z * S_ + blockIdx.x * 128) : (blockIdx.x * 128);
    const size_t nb = (size_t)blockIdx.y * 128;   // B row base (n)

    // cp.async per-thread assignments: 4 x 16B per chunk
    const __nv_bfloat16* gsrc[4];
    uint32_t sdst[4];
    #pragma unroll
    for (int j = 0; j < 4; j++) {
        int idx = tid + j * 256;          // 0..1023
        int arr = idx >> 8;               // 0:Ah 1:Al 2:Bh 3:Bl
        int rc  = idx & 255;
        int row = rc >> 1;
        int c   = (rc & 1) * 8;           // elem offset (16B)
        const __nv_bfloat16* base =
            (arr == 0) ? Ah : (arr == 1) ? Al : (arr == 2) ? Bh : Bl;
        size_t rbase = (arr < 2) ? (size_t)(mg + row) : (nb + row);
        gsrc[j] = base + rbase * D_ + c;
        sdst[j] = smem_u32(&smem[0][arr][row * LDA + c]);
    }

    // ldmatrix lane addressing (stage 0 bases; add stage offset later)
    const int ar = (lane & 7) + ((lane >> 3) & 1) * 8;
    const int ak = (lane >> 4) * 8;
    const int br = (lane & 7) + ((lane >> 4) & 1) * 8;
    const int bk = ((lane >> 3) & 1) * 8;
    uint32_t aaddr[2][2], baddr[2][4];
    #pragma unroll
    for (int hl = 0; hl < 2; hl++) {
        #pragma unroll
        for (int fm = 0; fm < 2; fm++)
            aaddr[hl][fm] = smem_u32(&smem[0][hl][(wm * 32 + fm * 16 + ar) * LDA + ak]);
        #pragma unroll
        for (int fn = 0; fn < 4; fn++)
            baddr[hl][fn] = smem_u32(&smem[0][2 + hl][(wn * 64 + fn * 16 + br) * LDA + bk]);
    }

    float acc[2][8][4];
    #pragma unroll
    for (int fm = 0; fm < 2; fm++)
        #pragma unroll
        for (int n2 = 0; n2 < 8; n2++)
            #pragma unroll
            for (int q = 0; q < 4; q++) acc[fm][n2][q] = 0.f;

    // preload chunk 0 into stage 0
    #pragma unroll
    for (int j = 0; j < 4; j++) cp16(sdst[j], gsrc[j]);
    CP_COMMIT();

    const int NC = D_ / 16;  // 64
    for (int kc = 0; kc < NC; kc++) {
        const int st = kc & 1;
        if (kc + 1 < NC) {
            const uint32_t so = (uint32_t)((st ^ 1) * STAGE_BYTES);
            #pragma unroll
            for (int j = 0; j < 4; j++) cp16(sdst[j] + so, gsrc[j] + (kc + 1) * 16);
            CP_COMMIT();
            CP_WAIT(1);
        } else {
            CP_WAIT(0);
        }
        __syncthreads();

        const uint32_t so = (uint32_t)(st * STAGE_BYTES);
        uint32_t afh[2][4], afl[2][4], bfh[4][4], bfl[4][4];
        #pragma unroll
        for (int fm = 0; fm < 2; fm++) {
            ldmx4(afh[fm], aaddr[0][fm] + so);
            ldmx4(afl[fm], aaddr[1][fm] + so);
        }
        #pragma unroll
        for (int fn = 0; fn < 4; fn++) {
            ldmx4(bfh[fn], baddr[0][fn] + so);
            ldmx4(bfl[fn], baddr[1][fn] + so);
        }
        #pragma unroll
        for (int fm = 0; fm < 2; fm++)
            #pragma unroll
            for (int fn = 0; fn < 4; fn++)
                #pragma unroll
                for (int hf = 0; hf < 2; hf++) {
                    const int n2 = fn * 2 + hf;
                    mma16816(acc[fm][n2], afh[fm], bfh[fn][hf * 2], bfh[fn][hf * 2 + 1]);
                    mma16816(acc[fm][n2], afh[fm], bfl[fn][hf * 2], bfl[fn][hf * 2 + 1]);
                    mma16816(acc[fm][n2], afl[fm], bfh[fn][hf * 2], bfh[fn][hf * 2 + 1]);
                }
        __syncthreads();
    }

    // epilogue
    const int g  = lane >> 2;
    const int t2 = (lane & 3) * 2;
    if (mode < 3) {
        // warp's 64 n-cols == one head
        float* Cw = C + (((size_t)blockIdx.z * H_ + 2 * blockIdx.y + wn) * S_ +
                         blockIdx.x * 128 + wm * 32) * 64;
        #pragma unroll
        for (int fm = 0; fm < 2; fm++)
            #pragma unroll
            for (int n2 = 0; n2 < 8; n2++) {
                const int col = n2 * 8 + t2;
                *(float2*)&Cw[(fm * 16 + g) * 64 + col]     = make_float2(acc[fm][n2][0], acc[fm][n2][1]);
                *(float2*)&Cw[(fm * 16 + g + 8) * 64 + col] = make_float2(acc[fm][n2][2], acc[fm][n2][3]);
            }
    } else {
        float* Cw = C + ((size_t)blockIdx.x * 128 + wm * 32) * D_ + blockIdx.y * 128 + wn * 64;
        #pragma unroll
        for (int fm = 0; fm < 2; fm++)
            #pragma unroll
            for (int n2 = 0; n2 < 8; n2++) {
                const int col = n2 * 8 + t2;
                *(float2*)&Cw[(fm * 16 + g) * D_ + col]     = make_float2(acc[fm][n2][0], acc[fm][n2][1]);
                *(float2*)&Cw[(fm * 16 + g + 8) * D_ + col] = make_float2(acc[fm][n2][2], acc[fm][n2][3]);
            }
    }
}

// ----------------- flash attention (fp32, f32x2 packed math) ---------------
__global__ __launch_bounds__(128, 4) void flash_kernel() {
    __shared__ float Qs[64 * 64];
    __shared__ float KP[64 * 64];
    __shared__ float Vs[64 * 64];

    const int h = blockIdx.y, b = blockIdx.z;
    const int q0 = blockIdx.x * 64;
    const size_t bh = ((size_t)b * H_ + h) * S_;
    const float* qh = g_q + bh * DK_;
    const float* kh = g_k + bh * DK_;
    const float* vh = g_v + bh * DK_;

    const int tid = threadIdx.x;
    const int tx = tid & 15;
    const int ty = tid >> 4;
    const int r = tid & 63;
    const int dbase = (tid >> 6) * 32;

    #pragma unroll
    for (int p = 0; p < 8; p++) {
        const int dd = dbase + p * 4;
        float4 t = *(const float4*)&qh[(size_t)(q0 + r) * DK_ + dd];
        Qs[(dd + 0) * 64 + r] = t.x;
        Qs[(dd + 1) * 64 + r] = t.y;
        Qs[(dd + 2) * 64 + r] = t.z;
        Qs[(dd + 3) * 64 + r] = t.w;
    }

    unsigned long long O2[8][2];
    float mi[8], li[8];
    #pragma unroll
    for (int i = 0; i < 8; i++) { mi[i] = -INFINITY; li[i] = 0.f; O2[i][0] = 0ull; O2[i][1] = 0ull; }

    for (int t0 = 0; t0 < S_; t0 += 64) {
        __syncthreads();
        #pragma unroll
        for (int p = 0; p < 8; p++) {
            const int dd = dbase + p * 4;
            float4 kk = *(const float4*)&kh[(size_t)(t0 + r) * DK_ + dd];
            KP[(dd + 0) * 64 + r] = kk.x;
            KP[(dd + 1) * 64 + r] = kk.y;
            KP[(dd + 2) * 64 + r] = kk.z;
            KP[(dd + 3) * 64 + r] = kk.w;
            const int u = dd >> 2;
            float4 vv = *(const float4*)&vh[(size_t)(t0 + r) * DK_ + dd];
            *(float4*)&Vs[r * 64 + ((u ^ (r & 15)) << 2)] = vv;
        }
        __syncthreads();

        unsigned long long acc[4][4];
        #pragma unroll
        for (int p = 0; p < 4; p++)
            #pragma unroll
            for (int j = 0; j < 4; j++) acc[p][j] = 0ull;

        #pragma unroll 8
        for (int dd = 0; dd < 64; dd++) {
            float4 a0 = *(const float4*)&Qs[dd * 64 + ty * 8];
            float4 a1 = *(const float4*)&Qs[dd * 64 + ty * 8 + 4];
            float4 bv = *(const float4*)&KP[dd * 64 + tx * 4];
            unsigned long long ap[4], bp[4];
            ap[0] = pk2(a0.x, a0.y); ap[1] = pk2(a0.z, a0.w);
            ap[2] = pk2(a1.x, a1.y); ap[3] = pk2(a1.z, a1.w);
            bp[0] = pk2(bv.x, bv.x); bp[1] = pk2(bv.y, bv.y);
            bp[2] = pk2(bv.z, bv.z); bp[3] = pk2(bv.w, bv.w);
            #pragma unroll
            for (int p = 0; p < 4; p++)
                #pragma unroll
                for (int j = 0; j < 4; j++)
                    acc[p][j] = fma2(ap[p], bp[j], acc[p][j]);
        }

        float s[8][4], al[8];
        #pragma unroll
        for (int p = 0; p < 4; p++)
            #pragma unroll
            for (int j = 0; j < 4; j++) upk2(acc[p][j], s[2 * p][j], s[2 * p + 1][j]);

        #pragma unroll
        for (int i = 0; i < 8; i++) {
            float mx = fmaxf(fmaxf(s[i][0], s[i][1]), fmaxf(s[i][2], s[i][3])) * 0.125f;
            #pragma unroll
            for (int off = 8; off >= 1; off >>= 1)
                mx = fmaxf(mx, __shfl_xor_sync(0xffffffffu, mx, off));
            const float mnew = fmaxf(mi[i], mx);
            al[i] = __expf(mi[i] - mnew);
            float rs = 0.f;
            #pragma unroll
            for (int j = 0; j < 4; j++) { s[i][j] = __expf(s[i][j] * 0.125f - mnew); rs += s[i][j]; }
            #pragma unroll
            for (int off = 8; off >= 1; off >>= 1)
                rs += __shfl_xor_sync(0xffffffffu, rs, off);
            li[i] = li[i] * al[i] + rs;
            mi[i] = mnew;
        }

        __syncthreads();
        #pragma unroll
        for (int i = 0; i < 8; i++) {
            *(float4*)&KP[(ty * 8 + i) * 64 + tx * 4] =
                make_float4(s[i][0], s[i][1], s[i][2], s[i][3]);
            unsigned long long aa = pk2(al[i], al[i]);
            O2[i][0] = mul2(O2[i][0], aa);
            O2[i][1] = mul2(O2[i][1], aa);
        }
        __syncthreads();

        #pragma unroll 4
        for (int tt = 0; tt < 64; tt++) {
            float4 bv = *(const float4*)&Vs[tt * 64 + ((tx ^ (tt & 15)) << 2)];
            unsigned long long b01 = pk2(bv.x, bv.y), b23 = pk2(bv.z, bv.w);
            #pragma unroll
            for (int i = 0; i < 8; i++) {
                const float av = KP[(ty * 8 + i) * 64 + tt];
                unsigned long long aa = pk2(av, av);
                O2[i][0] = fma2(aa, b01, O2[i][0]);
                O2[i][1] = fma2(aa, b23, O2[i][1]);
            }
        }
    }

    #pragma unroll
    for (int i = 0; i < 8; i++) {
        float o0, o1, o2, o3;
        upk2(O2[i][0], o0, o1);
        upk2(O2[i][1], o2, o3);
        const float inv = 1.0f / li[i];
        o0 *= inv; o1 *= inv; o2 *= inv; o3 *= inv;
        const int row = q0 + ty * 8 + i;
        const size_t base = ((size_t)(b * S_ + row)) * (H_ * DK_) + h * DK_ + tx * 4;
        uint16_t h0, h1, h2, h3, l0, l1, l2, l3;
        split_bf16(o0, h0, l0); split_bf16(o1, h1, l1);
        split_bf16(o2, h2, l2); split_bf16(o3, h3, l3);
        uint2 hv, lv;
        hv.x = (uint32_t)h0 | ((uint32_t)h1 << 16); hv.y = (uint32_t)h2 | ((uint32_t)h3 << 16);
        lv.x = (uint32_t)l0 | ((uint32_t)l1 << 16); lv.y = (uint32_t)l2 | ((uint32_t)l3 << 16);
        *(uint2*)(g_attn_hi + base) = hv;
        *(uint2*)(g_attn_lo + base) = lv;
    }
}

// ---------------------------------------------------------------------------
extern "C" void kernel_launch(void* const* d_in, const int* in_sizes, int n_in,
                              void* d_out, int out_size) {
    const float* x  = (const float*)d_in[0];
    const float* wq = (const float*)d_in[1];
    const float* wk = (const float*)d_in[2];
    const float* wv = (const float*)d_in[3];
    const float* wo = (const float*)d_in[4];
    float* out = (float*)d_out;

    conv_x_kernel<<<(B_ * S_ * D_) / 4 / 256, 256>>>((const float4*)x);
    conv_w_kernel<<<512, 256>>>(wq, 0);
    conv_w_kernel<<<512, 256>>>(wk, 1);
    conv_w_kernel<<<512, 256>>>(wv, 2);
    conv_wo_kernel<<<512, 256>>>(wo);

    dim3 gp(S_ / 128, 8, B_);         // 16 x 8 x 4 = 512 CTAs
    gemm_kernel<<<gp, 256>>>(nullptr, 0);
    gemm_kernel<<<gp, 256>>>(nullptr, 1);
    gemm_kernel<<<gp, 256>>>(nullptr, 2);

    dim3 gf(S_ / 64, H_, B_);         // 32 x 16 x 4
    flash_kernel<<<gf, 128>>>();

    dim3 go((B_ * S_) / 128, 8, 1);   // 64 x 8 = 512 CTAs
    gemm_kernel<<<go, 256>>>(out, 3);
}